// round 12
// baseline (speedup 1.0000x reference)
#include <cuda_runtime.h>
#include <cuda_bf16.h>
#include <stdint.h>

#define TT 128
#define MAXB 4096

// ---------------- scratch ----------------
__device__ uint32_t g_h1b[(size_t)MAXB * TT * 32];  // layer1 bidi out, bf16x2 [B][T][32]
__device__ float    g_h2[MAXB * 32];                // layer2 concat [B][32]

// ---------------- helpers ----------------
__device__ __forceinline__ uint32_t bf2(float lo, float hi) {
    uint32_t r;
    asm("cvt.rn.bf16x2.f32 %0, %1, %2;" : "=r"(r) : "f"(hi), "f"(lo));
    return r;
}
__device__ __forceinline__ float tanhx(float x) {
    float y; asm("tanh.approx.f32 %0, %1;" : "=f"(y) : "f"(x)); return y;
}
__device__ __forceinline__ float sigx(float x) {
    return fmaf(tanhx(x * 0.5f), 0.5f, 0.5f);
}
__device__ __forceinline__ void mma_bf16(float* d, const uint4& a, uint32_t b0, uint32_t b1) {
    asm volatile(
        "mma.sync.aligned.m16n8k16.row.col.f32.bf16.bf16.f32 "
        "{%0,%1,%2,%3},{%4,%5,%6,%7},{%8,%9},{%0,%1,%2,%3};"
        : "+f"(d[0]), "+f"(d[1]), "+f"(d[2]), "+f"(d[3])
        : "r"(a.x), "r"(a.y), "r"(a.z), "r"(a.w), "r"(b0), "r"(b1));
}

// ================= layer 1: H=32, KIN=64, K=96 (KC=6), seq out (bf16) ========
// GATE-SPLIT: block = 256 thr = 8 warps = 4 element-groups x 2 gate-halves.
// Warp (q, gh): element group q (h elems [q*8,q*8+8)); gh=0 computes gates
// (i,f) = tiles {q, 4+q}; gh=1 computes (g,o) = tiles {8+q, 12+q}. 12 MMA each.
// gh=1 applies tanh(g)/sig(o) and ships them via smem; gh=0 combines, owns
// (c,h), feedback + hout. gh=1 also stages x and flushes hout to gmem.
// Two __syncthreads per step. grid (B/16, 2) -> 4096 warps.
__global__ void __launch_bounds__(256) lstm1_mma(
    const float* __restrict__ in,
    const float* __restrict__ Wf, const float* __restrict__ Uf, const float* __restrict__ bf_,
    const float* __restrict__ Wb, const float* __restrict__ Ub, const float* __restrict__ bb)
{
    __shared__ uint32_t Bsm[6 * 16 * 32 * 2];               // 24KB (init only)
    __shared__ __align__(16) uint32_t Asm[2 * 6 * 128];     // 6KB, 2 buffers
    __shared__ __align__(16) uint32_t houtS[2 * 288];       // 2.25KB, 2 buffers
    __shared__ __align__(8)  float    Exc[4 * 2 * 2 * 64];  // 4KB: [q][kind][rh][64]
    __shared__ float biasS[128];

    const int dir = blockIdx.y;
    const float* W    = dir ? Wb : Wf;
    const float* U    = dir ? Ub : Uf;
    const float* bias = dir ? bb : bf_;

    const int tid = threadIdx.x;
    const int w   = tid >> 5;
    const int q   = w & 3;        // element group
    const int gh  = w >> 2;       // gate half: 0 -> (i,f), 1 -> (g,o)
    const int l   = tid & 31;
    const int gid = l >> 2;
    const int tig = l & 3;

    // ---- build B fragments (bf16) ----
    for (int idx = tid; idx < 6 * 16 * 32 * 2; idx += 256) {
        const int which = idx & 1;
        const int lane  = (idx >> 1) & 31;
        const int nt    = (idx >> 6) & 15;
        const int kc    = idx >> 10;
        const int k = kc * 16 + which * 8 + 2 * (lane & 3);
        const int n = nt * 8 + (lane >> 2);
        const float v0 = (k     < 64) ? W[k * 128 + n]       : U[(k - 64) * 128 + n];
        const float v1 = (k + 1 < 64) ? W[(k + 1) * 128 + n] : U[(k - 63) * 128 + n];
        Bsm[idx] = bf2(v0, v1);
    }
    if (tid < 128) biasS[tid] = bias[tid];
    // zero h region of buffer 0 (kc 4,5 = 256 u32)
    if (tid < 256) Asm[512 + tid] = 0;
    __syncthreads();

    // ---- B to registers: warp (q, gh) -> tiles (gh*2+gg)*4 + q ----
    uint32_t Br[6][2][2];
    #pragma unroll
    for (int kc = 0; kc < 6; kc++)
        #pragma unroll
        for (int gg = 0; gg < 2; gg++) {
            const int base = ((kc * 16 + (gh * 2 + gg) * 4 + q) * 32 + l) * 2;
            Br[kc][gg][0] = Bsm[base];
            Br[kc][gg][1] = Bsm[base + 1];
        }

    float2 bz[2];
    #pragma unroll
    for (int gg = 0; gg < 2; gg++) {
        const int col = (gh * 2 + gg) * 32 + q * 8 + 2 * tig;
        bz[gg] = make_float2(biasS[col], biasS[col + 1]);
    }

    const int ws = blockIdx.x * 16;

    // gh=1 staging (R11 wide-load scheme): warp q stages kc=q
    const float* xL0 = in + (size_t)(ws + gid) * TT * 64 + q * 16 + 4 * tig;
    const float* xL1 = xL0 + (size_t)8 * TT * 64;
    const int srcLo = (l & ~3) | (tig >> 1);
    const int srcHi = srcLo + 2;
    const bool oddT = (tig & 1) != 0;

    // flush mapping (gh=1 threads; ft in [0,128))
    const int ft  = tid & 127;
    const int sF  = ft >> 3;
    const int ocF = ft & 7;

    float cc[4] = {0.f, 0.f, 0.f, 0.f};   // gh=0 only

    float4 v0, v1;   // gh=1 prefetch regs

    if (gh == 1) {   // prologue: stage x_0 into buffer 0; prefetch x_1
        const int tt0 = dir ? TT - 1 : 0;
        v0 = *(const float4*)(xL0 + (size_t)tt0 * 64);
        v1 = *(const float4*)(xL1 + (size_t)tt0 * 64);
        const uint32_t pa0 = bf2(v0.x, v0.y), pa1 = bf2(v0.z, v0.w);
        const uint32_t pb0 = bf2(v1.x, v1.y), pb1 = bf2(v1.z, v1.w);
        const uint32_t a0l = __shfl_sync(0xffffffffu, pa0, srcLo);
        const uint32_t a1l = __shfl_sync(0xffffffffu, pa1, srcLo);
        const uint32_t b0l = __shfl_sync(0xffffffffu, pb0, srcLo);
        const uint32_t b1l = __shfl_sync(0xffffffffu, pb1, srcLo);
        const uint32_t a0h = __shfl_sync(0xffffffffu, pa0, srcHi);
        const uint32_t a1h = __shfl_sync(0xffffffffu, pa1, srcHi);
        const uint32_t b0h = __shfl_sync(0xffffffffu, pb0, srcHi);
        const uint32_t b1h = __shfl_sync(0xffffffffu, pb1, srcHi);
        *(uint4*)(Asm + q * 128 + l * 4) = make_uint4(
            oddT ? a1l : a0l, oddT ? b1l : b0l,
            oddT ? a1h : a0h, oddT ? b1h : b0h);
        const int tt1 = dir ? TT - 2 : 1;
        v0 = *(const float4*)(xL0 + (size_t)tt1 * 64);
        v1 = *(const float4*)(xL1 + (size_t)tt1 * 64);
    }
    __syncthreads();

    for (int t = 0; t < TT; t++) {
        const int tt = dir ? TT - 1 - t : t;
        const uint32_t* Acur = Asm + (t & 1) * 768;
        uint32_t*       Anxt = Asm + ((t + 1) & 1) * 768;

        // ---- phase 1: MMA (both halves; 12 MMA each) ----
        float d[2][4];
        #pragma unroll
        for (int gg = 0; gg < 2; gg++) {
            d[gg][0] = bz[gg].x; d[gg][1] = bz[gg].y;
            d[gg][2] = bz[gg].x; d[gg][3] = bz[gg].y;
        }
        #pragma unroll
        for (int kc = 0; kc < 6; kc++) {
            const uint4 a = *((const uint4*)Acur + kc * 32 + l);
            mma_bf16(d[0], a, Br[kc][0][0], Br[kc][0][1]);
            mma_bf16(d[1], a, Br[kc][1][0], Br[kc][1][1]);
        }

        if (gh == 1) {
            // gates g (d[0]) and o (d[1]): apply nonlinearity, export
            #pragma unroll
            for (int rh = 0; rh < 2; rh++) {
                const float2 tg = make_float2(tanhx(d[0][2 * rh]), tanhx(d[0][2 * rh + 1]));
                const float2 so = make_float2(sigx(d[1][2 * rh]),  sigx(d[1][2 * rh + 1]));
                *(float2*)&Exc[((q * 2 + 0) * 2 + rh) * 64 + l * 2] = tg;
                *(float2*)&Exc[((q * 2 + 1) * 2 + rh) * 64 + l * 2] = so;
            }
        }
        __syncthreads();   // barrier 1: exchange visible

        if (gh == 0) {
            // gates i (d[0]) and f (d[1]); combine with imported tg/so
            uint32_t hp[2];
            #pragma unroll
            for (int rh = 0; rh < 2; rh++) {
                const float2 tg = *(const float2*)&Exc[((q * 2 + 0) * 2 + rh) * 64 + l * 2];
                const float2 so = *(const float2*)&Exc[((q * 2 + 1) * 2 + rh) * 64 + l * 2];
                float h0, h1;
                {
                    const int p = 2 * rh;
                    const float c = sigx(d[1][p]) * cc[p] + sigx(d[0][p]) * tg.x;
                    h0 = so.x * tanhx(c); cc[p] = c;
                }
                {
                    const int p = 2 * rh + 1;
                    const float c = sigx(d[1][p]) * cc[p] + sigx(d[0][p]) * tg.y;
                    h1 = so.y * tanhx(c); cc[p] = c;
                }
                hp[rh] = bf2(h0, h1);
                houtS[(t & 1) * 288 + (gid + 8 * rh) * 18 + q * 4 + tig] = hp[rh];
            }
            *(uint2*)(Anxt + (4 + (q >> 1)) * 128 + l * 4 + (q & 1) * 2)
                = make_uint2(hp[0], hp[1]);
        } else {
            // flush hout(t-1) to gmem
            if (t > 0) {
                const int tprev = dir ? tt + 1 : tt - 1;
                const uint2 hv = *(const uint2*)&houtS[((t - 1) & 1) * 288 + sF * 18 + ocF * 2];
                *(uint2*)&g_h1b[((size_t)(ws + sF) * TT + tprev) * 32 + dir * 16 + ocF * 2] = hv;
            }
            // stage x_{t+1}; prefetch x_{t+2}
            if (t + 1 < TT) {
                const uint32_t pa0 = bf2(v0.x, v0.y), pa1 = bf2(v0.z, v0.w);
                const uint32_t pb0 = bf2(v1.x, v1.y), pb1 = bf2(v1.z, v1.w);
                const uint32_t a0l = __shfl_sync(0xffffffffu, pa0, srcLo);
                const uint32_t a1l = __shfl_sync(0xffffffffu, pa1, srcLo);
                const uint32_t b0l = __shfl_sync(0xffffffffu, pb0, srcLo);
                const uint32_t b1l = __shfl_sync(0xffffffffu, pb1, srcLo);
                const uint32_t a0h = __shfl_sync(0xffffffffu, pa0, srcHi);
                const uint32_t a1h = __shfl_sync(0xffffffffu, pa1, srcHi);
                const uint32_t b0h = __shfl_sync(0xffffffffu, pb0, srcHi);
                const uint32_t b1h = __shfl_sync(0xffffffffu, pb1, srcHi);
                *(uint4*)(Anxt + q * 128 + l * 4) = make_uint4(
                    oddT ? a1l : a0l, oddT ? b1l : b0l,
                    oddT ? a1h : a0h, oddT ? b1h : b0h);
                if (t + 2 < TT) {
                    const int tt2 = dir ? tt - 2 : tt + 2;
                    v0 = *(const float4*)(xL0 + (size_t)tt2 * 64);
                    v1 = *(const float4*)(xL1 + (size_t)tt2 * 64);
                }
            }
        }
        __syncthreads();   // barrier 2: A[(t+1)&1] complete
    }

    // final flush (t = TT-1) by first 128 threads
    if (tid < 128) {
        const int tlast = dir ? 0 : TT - 1;
        const uint2 hv = *(const uint2*)&houtS[((TT - 1) & 1) * 288 + (tid >> 3) * 18 + (tid & 7) * 2];
        *(uint2*)&g_h1b[((size_t)(ws + (tid >> 3)) * TT + tlast) * 32 + dir * 16 + (tid & 7) * 2] = hv;
    }
}

// ================= layer 2: H=16, K=80 (KC=5), last-h only ===================
// GATE-SPLIT: block = 128 thr = 4 warps = 2 element-halves x 2 gate-halves.
// Warp (nh, gh): gh=0 gates (i,f) tiles {nh, 2+nh}; gh=1 gates (g,o) tiles
// {4+nh, 6+nh}. 10 MMA each. Same exchange scheme as lstm1.
// grid (B/16, 2) -> 2048 warps.
__global__ void __launch_bounds__(128) lstm2_mma(
    const float* __restrict__ W2f, const float* __restrict__ U2f, const float* __restrict__ b2f,
    const float* __restrict__ W2b, const float* __restrict__ U2b, const float* __restrict__ b2b)
{
    __shared__ uint32_t Bsm[5 * 8 * 32 * 2];               // 10KB (init only)
    __shared__ __align__(16) uint32_t Asm[2 * 5 * 128];    // 5KB, 2 buffers
    __shared__ __align__(8)  float    Exc[2 * 2 * 2 * 64]; // 2KB: [nh][kind][rh][64]
    __shared__ float biasS[64];

    const int dir = blockIdx.y;
    const float* W    = dir ? W2b : W2f;
    const float* U    = dir ? U2b : U2f;
    const float* bias = dir ? b2b : b2f;

    const int tid = threadIdx.x;
    const int w   = tid >> 5;
    const int nh  = w & 1;        // element half
    const int gh  = w >> 1;       // gate half
    const int l   = tid & 31;
    const int gid = l >> 2;
    const int tig = l & 3;

    for (int idx = tid; idx < 5 * 8 * 32 * 2; idx += 128) {
        const int which = idx & 1;
        const int lane  = (idx >> 1) & 31;
        const int nt    = (idx >> 6) & 7;
        const int kc    = idx >> 9;
        const int k = kc * 16 + which * 8 + 2 * (lane & 3);
        const int n = nt * 8 + (lane >> 2);
        const float v0 = (k     < 64) ? W[k * 64 + n]       : U[(k - 64) * 64 + n];
        const float v1 = (k + 1 < 64) ? W[(k + 1) * 64 + n] : U[(k - 63) * 64 + n];
        Bsm[idx] = bf2(v0, v1);
    }
    if (tid < 64) biasS[tid] = bias[tid];
    if (tid < 128) Asm[4 * 128 + tid] = 0;   // h region of buffer 0
    __syncthreads();

    uint32_t Br[5][2][2];
    #pragma unroll
    for (int kc = 0; kc < 5; kc++)
        #pragma unroll
        for (int gg = 0; gg < 2; gg++) {
            const int base = ((kc * 8 + (gh * 2 + gg) * 2 + nh) * 32 + l) * 2;
            Br[kc][gg][0] = Bsm[base];
            Br[kc][gg][1] = Bsm[base + 1];
        }

    float2 bz[2];
    #pragma unroll
    for (int gg = 0; gg < 2; gg++) {
        const int col = (gh * 2 + gg) * 16 + nh * 8 + 2 * tig;
        bz[gg] = make_float2(biasS[col], biasS[col + 1]);
    }

    const int ws = blockIdx.x * 16;

    // gh=1 staging (R11 lstm2 scheme), 64 tasks on tids 64..127
    const int st   = tid & 63;
    const int kcS  = st >> 4;
    const int gidS = (st & 15) >> 1;
    const int tp   = st & 1;
    const int j0   = gidS * 4 + 2 * tp;
    const uint32_t* h0p = g_h1b + (size_t)(ws + gidS) * TT * 32 + kcS * 8 + 2 * tp;
    const uint32_t* h1p = h0p + (size_t)8 * TT * 32;

    float cc[4] = {0.f, 0.f, 0.f, 0.f};   // gh=0 only

    uint2 lo0, lo1, hi0, hi1;   // gh=1 prefetch
    if (gh == 1) {
        const int tt0 = dir ? TT - 1 : 0;
        lo0 = *(const uint2*)(h0p + (size_t)tt0 * 32);
        lo1 = *(const uint2*)(h1p + (size_t)tt0 * 32);
        hi0 = *(const uint2*)(h0p + (size_t)tt0 * 32 + 4);
        hi1 = *(const uint2*)(h1p + (size_t)tt0 * 32 + 4);
        *(uint4*)(Asm + kcS * 128 + j0 * 4)       = make_uint4(lo0.x, lo1.x, hi0.x, hi1.x);
        *(uint4*)(Asm + kcS * 128 + (j0 + 1) * 4) = make_uint4(lo0.y, lo1.y, hi0.y, hi1.y);
        const int tt1 = dir ? TT - 2 : 1;
        lo0 = *(const uint2*)(h0p + (size_t)tt1 * 32);
        lo1 = *(const uint2*)(h1p + (size_t)tt1 * 32);
        hi0 = *(const uint2*)(h0p + (size_t)tt1 * 32 + 4);
        hi1 = *(const uint2*)(h1p + (size_t)tt1 * 32 + 4);
    }
    __syncthreads();

    for (int t = 0; t < TT; t++) {
        const int tt = dir ? TT - 1 - t : t;
        const uint32_t* Acur = Asm + (t & 1) * 640;
        uint32_t*       Anxt = Asm + ((t + 1) & 1) * 640;

        float d[2][4];
        #pragma unroll
        for (int gg = 0; gg < 2; gg++) {
            d[gg][0] = bz[gg].x; d[gg][1] = bz[gg].y;
            d[gg][2] = bz[gg].x; d[gg][3] = bz[gg].y;
        }
        #pragma unroll
        for (int kc = 0; kc < 5; kc++) {
            const uint4 a = *((const uint4*)Acur + kc * 32 + l);
            mma_bf16(d[0], a, Br[kc][0][0], Br[kc][0][1]);
            mma_bf16(d[1], a, Br[kc][1][0], Br[kc][1][1]);
        }

        if (gh == 1) {
            #pragma unroll
            for (int rh = 0; rh < 2; rh++) {
                const float2 tg = make_float2(tanhx(d[0][2 * rh]), tanhx(d[0][2 * rh + 1]));
                const float2 so = make_float2(sigx(d[1][2 * rh]),  sigx(d[1][2 * rh + 1]));
                *(float2*)&Exc[((nh * 2 + 0) * 2 + rh) * 64 + l * 2] = tg;
                *(float2*)&Exc[((nh * 2 + 1) * 2 + rh) * 64 + l * 2] = so;
            }
        }
        __syncthreads();   // barrier 1

        if (gh == 0) {
            uint32_t hp[2];
            float hlast[4];
            #pragma unroll
            for (int rh = 0; rh < 2; rh++) {
                const float2 tg = *(const float2*)&Exc[((nh * 2 + 0) * 2 + rh) * 64 + l * 2];
                const float2 so = *(const float2*)&Exc[((nh * 2 + 1) * 2 + rh) * 64 + l * 2];
                float h0, h1;
                {
                    const int p = 2 * rh;
                    const float c = sigx(d[1][p]) * cc[p] + sigx(d[0][p]) * tg.x;
                    h0 = so.x * tanhx(c); cc[p] = c;
                }
                {
                    const int p = 2 * rh + 1;
                    const float c = sigx(d[1][p]) * cc[p] + sigx(d[0][p]) * tg.y;
                    h1 = so.y * tanhx(c); cc[p] = c;
                }
                hp[rh] = bf2(h0, h1);
                hlast[2 * rh] = h0; hlast[2 * rh + 1] = h1;
            }
            *(uint2*)(Anxt + 4 * 128 + l * 4 + nh * 2) = make_uint2(hp[0], hp[1]);

            if (t == TT - 1) {
                #pragma unroll
                for (int rh = 0; rh < 2; rh++) {
                    const int e0 = nh * 8 + 2 * tig;
                    *(float2*)&g_h2[(ws + gid + 8 * rh) * 32 + dir * 16 + e0]
                        = make_float2(hlast[2 * rh], hlast[2 * rh + 1]);
                }
            }
        } else {
            if (t + 1 < TT) {
                *(uint4*)(Anxt + kcS * 128 + j0 * 4)       = make_uint4(lo0.x, lo1.x, hi0.x, hi1.x);
                *(uint4*)(Anxt + kcS * 128 + (j0 + 1) * 4) = make_uint4(lo0.y, lo1.y, hi0.y, hi1.y);
                if (t + 2 < TT) {
                    const int tt2 = dir ? tt - 2 : tt + 2;
                    lo0 = *(const uint2*)(h0p + (size_t)tt2 * 32);
                    lo1 = *(const uint2*)(h1p + (size_t)tt2 * 32);
                    hi0 = *(const uint2*)(h0p + (size_t)tt2 * 32 + 4);
                    hi1 = *(const uint2*)(h1p + (size_t)tt2 * 32 + 4);
                }
            }
        }
        __syncthreads();   // barrier 2
    }
}

// ================= head: dense(8)+swish, dense(2)+sigmoid ================
__device__ __forceinline__ float sigf(float x) { return 1.0f / (1.0f + __expf(-x)); }

__global__ void head_kernel(
    const float* __restrict__ W3, const float* __restrict__ b3,
    const float* __restrict__ W4, const float* __restrict__ b4,
    float* __restrict__ out, int B)
{
    const int b = blockIdx.x * blockDim.x + threadIdx.x;
    if (b >= B) return;

    float xvv[32];
    #pragma unroll
    for (int i = 0; i < 32; i++) xvv[i] = g_h2[b * 32 + i];

    float y[8];
    #pragma unroll
    for (int o = 0; o < 8; o++) {
        float acc = b3[o];
        #pragma unroll
        for (int k = 0; k < 32; k++)
            acc = fmaf(xvv[k], W3[k * 8 + o], acc);
        y[o] = acc * sigf(acc);
    }

    #pragma unroll
    for (int m = 0; m < 2; m++) {
        float acc = b4[m];
        #pragma unroll
        for (int o = 0; o < 8; o++)
            acc = fmaf(y[o], W4[o * 2 + m], acc);
        out[b * 2 + m] = sigf(acc);
    }
}

// ================= launch ================
extern "C" void kernel_launch(void* const* d_in, const int* in_sizes, int n_in,
                              void* d_out, int out_size)
{
    const float* x   = (const float*)d_in[0];
    const float* W1f = (const float*)d_in[1];
    const float* U1f = (const float*)d_in[2];
    const float* b1f = (const float*)d_in[3];
    const float* W1b = (const float*)d_in[4];
    const float* U1b = (const float*)d_in[5];
    const float* b1b = (const float*)d_in[6];
    const float* W2f = (const float*)d_in[7];
    const float* U2f = (const float*)d_in[8];
    const float* b2f = (const float*)d_in[9];
    const float* W2b = (const float*)d_in[10];
    const float* U2b = (const float*)d_in[11];
    const float* b2b = (const float*)d_in[12];
    const float* W3  = (const float*)d_in[13];
    const float* b3  = (const float*)d_in[14];
    const float* W4  = (const float*)d_in[15];
    const float* b4  = (const float*)d_in[16];
    float* out = (float*)d_out;

    const int B = in_sizes[0] / (TT * 64);   // 4096

    lstm1_mma<<<dim3(B / 16, 2), 256>>>(x, W1f, U1f, b1f, W1b, U1b, b1b);
    lstm2_mma<<<dim3(B / 16, 2), 128>>>(W2f, U2f, b2f, W2b, U2b, b2b);
    head_kernel<<<(B + 255) / 256, 256>>>(W3, b3, W4, b4, out, B);
}

// round 13
// speedup vs baseline: 1.4347x; 1.4347x over previous
#include <cuda_runtime.h>
#include <cuda_bf16.h>
#include <stdint.h>

#define TT 128
#define MAXB 4096

// ---------------- scratch ----------------
__device__ uint32_t g_h1b[(size_t)MAXB * TT * 32];  // layer1 bidi out, bf16x2 [B][T][32]
__device__ float    g_h2[MAXB * 32];                // layer2 concat [B][32]

// ---------------- helpers ----------------
__device__ __forceinline__ uint32_t bf2(float lo, float hi) {
    uint32_t r;
    asm("cvt.rn.bf16x2.f32 %0, %1, %2;" : "=r"(r) : "f"(hi), "f"(lo));
    return r;
}
__device__ __forceinline__ float tanhx(float x) {
    float y; asm("tanh.approx.f32 %0, %1;" : "=f"(y) : "f"(x)); return y;
}
__device__ __forceinline__ float sigx(float x) {
    return fmaf(tanhx(x * 0.5f), 0.5f, 0.5f);
}
__device__ __forceinline__ void mma_bf16(float* d, const uint4& a, uint32_t b0, uint32_t b1) {
    asm volatile(
        "mma.sync.aligned.m16n8k16.row.col.f32.bf16.bf16.f32 "
        "{%0,%1,%2,%3},{%4,%5,%6,%7},{%8,%9},{%0,%1,%2,%3};"
        : "+f"(d[0]), "+f"(d[1]), "+f"(d[2]), "+f"(d[3])
        : "r"(a.x), "r"(a.y), "r"(a.z), "r"(a.w), "r"(b0), "r"(b1));
}

// ================= layer 1: H=32, KIN=64, K=96 (KC=6), seq out (bf16) ========
// R11 verbatim: 4-way N-split, B in regs, A double-buffered, 1 bar/step,
// wide x LDG.128 + shfl redistribution.
__global__ void __launch_bounds__(128) lstm1_mma(
    const float* __restrict__ in,
    const float* __restrict__ Wf, const float* __restrict__ Uf, const float* __restrict__ bf_,
    const float* __restrict__ Wb, const float* __restrict__ Ub, const float* __restrict__ bb)
{
    __shared__ uint32_t Bsm[6 * 16 * 32 * 2];               // 24KB (init only)
    __shared__ __align__(16) uint32_t Asm[2 * 6 * 32 * 4];  // 6KB, 2 buffers
    __shared__ __align__(16) uint32_t houtS[2 * 16 * 18];   // 2.25KB, 2 buffers
    __shared__ float biasS[128];

    const int dir = blockIdx.y;
    const float* W    = dir ? Wb : Wf;
    const float* U    = dir ? Ub : Uf;
    const float* bias = dir ? bb : bf_;

    const int tid = threadIdx.x;
    const int q   = tid >> 5;
    const int l   = tid & 31;
    const int gid = l >> 2;
    const int tig = l & 3;

    for (int idx = tid; idx < 6 * 16 * 32 * 2; idx += 128) {
        const int which = idx & 1;
        const int lane  = (idx >> 1) & 31;
        const int nt    = (idx >> 6) & 15;
        const int kc    = idx >> 10;
        const int k = kc * 16 + which * 8 + 2 * (lane & 3);
        const int n = nt * 8 + (lane >> 2);
        const float v0 = (k     < 64) ? W[k * 128 + n]       : U[(k - 64) * 128 + n];
        const float v1 = (k + 1 < 64) ? W[(k + 1) * 128 + n] : U[(k - 63) * 128 + n];
        Bsm[idx] = bf2(v0, v1);
    }
    if (tid < 128) biasS[tid] = bias[tid];
    for (int idx = tid; idx < 256; idx += 128) Asm[512 + idx] = 0;
    __syncthreads();

    uint32_t Br[6][4][2];
    #pragma unroll
    for (int kc = 0; kc < 6; kc++)
        #pragma unroll
        for (int g = 0; g < 4; g++) {
            const int base = ((kc * 16 + g * 4 + q) * 32 + l) * 2;
            Br[kc][g][0] = Bsm[base];
            Br[kc][g][1] = Bsm[base + 1];
        }

    float2 bz[4];
    #pragma unroll
    for (int g = 0; g < 4; g++) {
        const int col = g * 32 + q * 8 + 2 * tig;
        bz[g] = make_float2(biasS[col], biasS[col + 1]);
    }

    const int ws = blockIdx.x * 16;
    const float* xL0 = in + (size_t)(ws + gid) * TT * 64 + q * 16 + 4 * tig;
    const float* xL1 = xL0 + (size_t)8 * TT * 64;

    const int srcLo = (l & ~3) | (tig >> 1);
    const int srcHi = srcLo + 2;
    const bool oddT = (tig & 1) != 0;

    const int sF  = tid >> 3;
    const int ocF = tid & 7;

    float cc[4] = {0.f, 0.f, 0.f, 0.f};

    float4 v0, v1;

    {   // prologue: stage x_0 into buffer 0; prefetch x_1
        const int tt0 = dir ? TT - 1 : 0;
        v0 = *(const float4*)(xL0 + (size_t)tt0 * 64);
        v1 = *(const float4*)(xL1 + (size_t)tt0 * 64);
        const uint32_t pa0 = bf2(v0.x, v0.y), pa1 = bf2(v0.z, v0.w);
        const uint32_t pb0 = bf2(v1.x, v1.y), pb1 = bf2(v1.z, v1.w);
        const uint32_t a0l = __shfl_sync(0xffffffffu, pa0, srcLo);
        const uint32_t a1l = __shfl_sync(0xffffffffu, pa1, srcLo);
        const uint32_t b0l = __shfl_sync(0xffffffffu, pb0, srcLo);
        const uint32_t b1l = __shfl_sync(0xffffffffu, pb1, srcLo);
        const uint32_t a0h = __shfl_sync(0xffffffffu, pa0, srcHi);
        const uint32_t a1h = __shfl_sync(0xffffffffu, pa1, srcHi);
        const uint32_t b0h = __shfl_sync(0xffffffffu, pb0, srcHi);
        const uint32_t b1h = __shfl_sync(0xffffffffu, pb1, srcHi);
        *(uint4*)(Asm + q * 128 + l * 4) = make_uint4(
            oddT ? a1l : a0l, oddT ? b1l : b0l,
            oddT ? a1h : a0h, oddT ? b1h : b0h);
        if (TT > 1) {
            const int tt1 = dir ? TT - 2 : 1;
            v0 = *(const float4*)(xL0 + (size_t)tt1 * 64);
            v1 = *(const float4*)(xL1 + (size_t)tt1 * 64);
        }
    }
    __syncthreads();

    for (int t = 0; t < TT; t++) {
        const int tt = dir ? TT - 1 - t : t;
        const uint32_t* Acur = Asm + (t & 1) * 768;
        uint32_t*       Anxt = Asm + ((t + 1) & 1) * 768;

        float d[4][4];
        #pragma unroll
        for (int g = 0; g < 4; g++) {
            d[g][0] = bz[g].x; d[g][1] = bz[g].y;
            d[g][2] = bz[g].x; d[g][3] = bz[g].y;
        }
        #pragma unroll
        for (int kc = 0; kc < 6; kc++) {
            const uint4 a = *((const uint4*)Acur + kc * 32 + l);
            #pragma unroll
            for (int g = 0; g < 4; g++)
                mma_bf16(d[g], a, Br[kc][g][0], Br[kc][g][1]);
        }

        if (t > 0) {
            const int tprev = dir ? tt + 1 : tt - 1;
            const uint2 hv = *(const uint2*)&houtS[((t - 1) & 1) * 288 + sF * 18 + ocF * 2];
            *(uint2*)&g_h1b[((size_t)(ws + sF) * TT + tprev) * 32 + dir * 16 + ocF * 2] = hv;
        }

        if (t + 1 < TT) {
            const uint32_t pa0 = bf2(v0.x, v0.y), pa1 = bf2(v0.z, v0.w);
            const uint32_t pb0 = bf2(v1.x, v1.y), pb1 = bf2(v1.z, v1.w);
            const uint32_t a0l = __shfl_sync(0xffffffffu, pa0, srcLo);
            const uint32_t a1l = __shfl_sync(0xffffffffu, pa1, srcLo);
            const uint32_t b0l = __shfl_sync(0xffffffffu, pb0, srcLo);
            const uint32_t b1l = __shfl_sync(0xffffffffu, pb1, srcLo);
            const uint32_t a0h = __shfl_sync(0xffffffffu, pa0, srcHi);
            const uint32_t a1h = __shfl_sync(0xffffffffu, pa1, srcHi);
            const uint32_t b0h = __shfl_sync(0xffffffffu, pb0, srcHi);
            const uint32_t b1h = __shfl_sync(0xffffffffu, pb1, srcHi);
            *(uint4*)(Anxt + q * 128 + l * 4) = make_uint4(
                oddT ? a1l : a0l, oddT ? b1l : b0l,
                oddT ? a1h : a0h, oddT ? b1h : b0h);
            if (t + 2 < TT) {
                const int tt2 = dir ? tt - 2 : tt + 2;
                v0 = *(const float4*)(xL0 + (size_t)tt2 * 64);
                v1 = *(const float4*)(xL1 + (size_t)tt2 * 64);
            }
        }

        uint32_t hp[2];
        #pragma unroll
        for (int rh = 0; rh < 2; rh++) {
            float h0, h1;
            {
                const int p = rh * 2;
                const float ig = sigx(d[0][p]);
                const float fg = sigx(d[1][p]);
                const float gg = tanhx(d[2][p]);
                const float og = sigx(d[3][p]);
                const float c  = fg * cc[p] + ig * gg;
                h0 = og * tanhx(c); cc[p] = c;
            }
            {
                const int p = rh * 2 + 1;
                const float ig = sigx(d[0][p]);
                const float fg = sigx(d[1][p]);
                const float gg = tanhx(d[2][p]);
                const float og = sigx(d[3][p]);
                const float c  = fg * cc[p] + ig * gg;
                h1 = og * tanhx(c); cc[p] = c;
            }
            hp[rh] = bf2(h0, h1);
            houtS[(t & 1) * 288 + (gid + 8 * rh) * 18 + q * 4 + tig] = hp[rh];
        }
        *(uint2*)(Anxt + (4 + (q >> 1)) * 128 + l * 4 + (q & 1) * 2)
            = make_uint2(hp[0], hp[1]);

        __syncthreads();
    }

    {
        const int tlast = dir ? 0 : TT - 1;
        const uint2 hv = *(const uint2*)&houtS[((TT - 1) & 1) * 288 + sF * 18 + ocF * 2];
        *(uint2*)&g_h1b[((size_t)(ws + sF) * TT + tlast) * 32 + dir * 16 + ocF * 2] = hv;
    }
}

// ================= layer 2: H=16, K=80 (KC=5), last-h only, M=16 =============
// R11 structure + SPLIT ACCUMULATOR CHAINS: each gate's 5-deep dependent MMA
// chain becomes 3+2 on two accumulator sets (d = kc 0-2 + bias, d2 = kc 3-4),
// combined with FADDs before the activations. Cuts the per-step MMA latency
// chain ~40%.
__global__ void __launch_bounds__(64) lstm2_mma(
    const float* __restrict__ W2f, const float* __restrict__ U2f, const float* __restrict__ b2f,
    const float* __restrict__ W2b, const float* __restrict__ U2b, const float* __restrict__ b2b)
{
    __shared__ uint32_t Bsm[5 * 8 * 32 * 2];               // 10KB (init only)
    __shared__ __align__(16) uint32_t Asm[2 * 5 * 128];    // 5KB, 2 buffers
    __shared__ float biasS[64];

    const int dir = blockIdx.y;
    const float* W    = dir ? W2b : W2f;
    const float* U    = dir ? U2b : U2f;
    const float* bias = dir ? b2b : b2f;

    const int tid  = threadIdx.x;
    const int half = tid >> 5;
    const int l    = tid & 31;
    const int gid  = l >> 2;
    const int tig  = l & 3;

    for (int idx = tid; idx < 5 * 8 * 32 * 2; idx += 64) {
        const int which = idx & 1;
        const int lane  = (idx >> 1) & 31;
        const int nt    = (idx >> 6) & 7;
        const int kc    = idx >> 9;
        const int k = kc * 16 + which * 8 + 2 * (lane & 3);
        const int n = nt * 8 + (lane >> 2);
        const float v0 = (k     < 64) ? W[k * 64 + n]       : U[(k - 64) * 64 + n];
        const float v1 = (k + 1 < 64) ? W[(k + 1) * 64 + n] : U[(k - 63) * 64 + n];
        Bsm[idx] = bf2(v0, v1);
    }
    if (tid < 64) biasS[tid] = bias[tid];
    for (int idx = tid; idx < 128; idx += 64) Asm[4 * 128 + idx] = 0;
    __syncthreads();

    uint32_t Br[5][4][2];
    #pragma unroll
    for (int kc = 0; kc < 5; kc++)
        #pragma unroll
        for (int g = 0; g < 4; g++) {
            const int base = ((kc * 8 + g * 2 + half) * 32 + l) * 2;
            Br[kc][g][0] = Bsm[base];
            Br[kc][g][1] = Bsm[base + 1];
        }

    float2 bz[4];
    #pragma unroll
    for (int g = 0; g < 4; g++) {
        const int col = g * 16 + half * 8 + 2 * tig;
        bz[g] = make_float2(biasS[col], biasS[col + 1]);
    }

    const int ws = blockIdx.x * 16;

    const int kcS  = tid >> 4;
    const int gidS = (tid & 15) >> 1;
    const int tp   = tid & 1;
    const int j0   = gidS * 4 + 2 * tp;
    const uint32_t* h0p = g_h1b + (size_t)(ws + gidS) * TT * 32 + kcS * 8 + 2 * tp;
    const uint32_t* h1p = h0p + (size_t)8 * TT * 32;

    float cc[4] = {0.f, 0.f, 0.f, 0.f};

    uint2 lo0, lo1, hi0, hi1;
    {
        const int tt0 = dir ? TT - 1 : 0;
        lo0 = *(const uint2*)(h0p + (size_t)tt0 * 32);
        lo1 = *(const uint2*)(h1p + (size_t)tt0 * 32);
        hi0 = *(const uint2*)(h0p + (size_t)tt0 * 32 + 4);
        hi1 = *(const uint2*)(h1p + (size_t)tt0 * 32 + 4);
        *(uint4*)(Asm + kcS * 128 + j0 * 4)       = make_uint4(lo0.x, lo1.x, hi0.x, hi1.x);
        *(uint4*)(Asm + kcS * 128 + (j0 + 1) * 4) = make_uint4(lo0.y, lo1.y, hi0.y, hi1.y);
        const int tt1 = dir ? TT - 2 : 1;
        lo0 = *(const uint2*)(h0p + (size_t)tt1 * 32);
        lo1 = *(const uint2*)(h1p + (size_t)tt1 * 32);
        hi0 = *(const uint2*)(h0p + (size_t)tt1 * 32 + 4);
        hi1 = *(const uint2*)(h1p + (size_t)tt1 * 32 + 4);
    }
    __syncthreads();

    for (int t = 0; t < TT; t++) {
        const int tt = dir ? TT - 1 - t : t;
        const uint32_t* Acur = Asm + (t & 1) * 640;
        uint32_t*       Anxt = Asm + ((t + 1) & 1) * 640;

        // split accumulators: d <- bias + kc{0,1,2};  d2 <- kc{3,4}
        float d[4][4], d2[4][4];
        #pragma unroll
        for (int g = 0; g < 4; g++) {
            d[g][0] = bz[g].x; d[g][1] = bz[g].y;
            d[g][2] = bz[g].x; d[g][3] = bz[g].y;
            d2[g][0] = 0.f; d2[g][1] = 0.f; d2[g][2] = 0.f; d2[g][3] = 0.f;
        }
        #pragma unroll
        for (int kc = 0; kc < 3; kc++) {
            const uint4 a = *((const uint4*)Acur + kc * 32 + l);
            #pragma unroll
            for (int g = 0; g < 4; g++)
                mma_bf16(d[g], a, Br[kc][g][0], Br[kc][g][1]);
        }
        #pragma unroll
        for (int kc = 3; kc < 5; kc++) {
            const uint4 a = *((const uint4*)Acur + kc * 32 + l);
            #pragma unroll
            for (int g = 0; g < 4; g++)
                mma_bf16(d2[g], a, Br[kc][g][0], Br[kc][g][1]);
        }

        if (t + 1 < TT) {
            *(uint4*)(Anxt + kcS * 128 + j0 * 4)       = make_uint4(lo0.x, lo1.x, hi0.x, hi1.x);
            *(uint4*)(Anxt + kcS * 128 + (j0 + 1) * 4) = make_uint4(lo0.y, lo1.y, hi0.y, hi1.y);
            if (t + 2 < TT) {
                const int tt2 = dir ? tt - 2 : tt + 2;
                lo0 = *(const uint2*)(h0p + (size_t)tt2 * 32);
                lo1 = *(const uint2*)(h1p + (size_t)tt2 * 32);
                hi0 = *(const uint2*)(h0p + (size_t)tt2 * 32 + 4);
                hi1 = *(const uint2*)(h1p + (size_t)tt2 * 32 + 4);
            }
        }

        uint32_t hp[2];
        float hlast[4];
        #pragma unroll
        for (int rh = 0; rh < 2; rh++) {
            float h0, h1;
            {
                const int p = rh * 2;
                const float ig = sigx(d[0][p] + d2[0][p]);
                const float fg = sigx(d[1][p] + d2[1][p]);
                const float gg = tanhx(d[2][p] + d2[2][p]);
                const float og = sigx(d[3][p] + d2[3][p]);
                const float c  = fg * cc[p] + ig * gg;
                h0 = og * tanhx(c); cc[p] = c;
            }
            {
                const int p = rh * 2 + 1;
                const float ig = sigx(d[0][p] + d2[0][p]);
                const float fg = sigx(d[1][p] + d2[1][p]);
                const float gg = tanhx(d[2][p] + d2[2][p]);
                const float og = sigx(d[3][p] + d2[3][p]);
                const float c  = fg * cc[p] + ig * gg;
                h1 = og * tanhx(c); cc[p] = c;
            }
            hp[rh] = bf2(h0, h1);
            hlast[rh * 2] = h0; hlast[rh * 2 + 1] = h1;
        }
        *(uint2*)(Anxt + 4 * 128 + l * 4 + half * 2) = make_uint2(hp[0], hp[1]);

        if (t == TT - 1) {
            #pragma unroll
            for (int rh = 0; rh < 2; rh++) {
                const int e0 = half * 8 + 2 * tig;
                *(float2*)&g_h2[(ws + gid + 8 * rh) * 32 + dir * 16 + e0]
                    = make_float2(hlast[rh * 2], hlast[rh * 2 + 1]);
            }
        }

        __syncthreads();
    }
}

// ================= head: dense(8)+swish, dense(2)+sigmoid ================
__device__ __forceinline__ float sigf(float x) { return 1.0f / (1.0f + __expf(-x)); }

__global__ void head_kernel(
    const float* __restrict__ W3, const float* __restrict__ b3,
    const float* __restrict__ W4, const float* __restrict__ b4,
    float* __restrict__ out, int B)
{
    const int b = blockIdx.x * blockDim.x + threadIdx.x;
    if (b >= B) return;

    float xvv[32];
    #pragma unroll
    for (int i = 0; i < 32; i++) xvv[i] = g_h2[b * 32 + i];

    float y[8];
    #pragma unroll
    for (int o = 0; o < 8; o++) {
        float acc = b3[o];
        #pragma unroll
        for (int k = 0; k < 32; k++)
            acc = fmaf(xvv[k], W3[k * 8 + o], acc);
        y[o] = acc * sigf(acc);
    }

    #pragma unroll
    for (int m = 0; m < 2; m++) {
        float acc = b4[m];
        #pragma unroll
        for (int o = 0; o < 8; o++)
            acc = fmaf(y[o], W4[o * 2 + m], acc);
        out[b * 2 + m] = sigf(acc);
    }
}

// ================= launch ================
extern "C" void kernel_launch(void* const* d_in, const int* in_sizes, int n_in,
                              void* d_out, int out_size)
{
    const float* x   = (const float*)d_in[0];
    const float* W1f = (const float*)d_in[1];
    const float* U1f = (const float*)d_in[2];
    const float* b1f = (const float*)d_in[3];
    const float* W1b = (const float*)d_in[4];
    const float* U1b = (const float*)d_in[5];
    const float* b1b = (const float*)d_in[6];
    const float* W2f = (const float*)d_in[7];
    const float* U2f = (const float*)d_in[8];
    const float* b2f = (const float*)d_in[9];
    const float* W2b = (const float*)d_in[10];
    const float* U2b = (const float*)d_in[11];
    const float* b2b = (const float*)d_in[12];
    const float* W3  = (const float*)d_in[13];
    const float* b3  = (const float*)d_in[14];
    const float* W4  = (const float*)d_in[15];
    const float* b4  = (const float*)d_in[16];
    float* out = (float*)d_out;

    const int B = in_sizes[0] / (TT * 64);   // 4096

    lstm1_mma<<<dim3(B / 16, 2), 128>>>(x, W1f, U1f, b1f, W1b, U1b, b1b);
    lstm2_mma<<<dim3(B / 16, 2), 64>>>(W2f, U2f, b2f, W2b, U2b, b2b);
    head_kernel<<<(B + 255) / 256, 256>>>(W3, b3, W4, b4, out, B);
}